// round 6
// baseline (speedup 1.0000x reference)
#include <cuda_runtime.h>
#include <math.h>

#define NUM_BLOCKS 1184
#define NUM_THREADS 256
#define CHUNK_F4 1024LL   // float4 per chunk per input (16 KB per input)

__device__ float g_partials[NUM_BLOCKS];
__device__ unsigned int g_ticket;   // zero-init; reset by last block each run
__device__ unsigned int g_chunk;    // zero-init; reset by last block each run

__global__ __launch_bounds__(NUM_THREADS)
void lik_pipe_kernel(const float* __restrict__ o,
                     const float* __restrict__ x,
                     const float* __restrict__ noise_p,
                     float* __restrict__ out,
                     long long n4, double nd)
{
    const float4* __restrict__ o4 = (const float4*)o;
    const float4* __restrict__ x4 = (const float4*)x;

    // s_base[0], s_base[1]: double-buffered future chunk bases.
    // s_base[2]: the prologue's current chunk.
    __shared__ long long s_base[3];
    int lane = threadIdx.x & 31;
    int wid  = threadIdx.x >> 5;

    if (threadIdx.x == 0) {
        s_base[2] = (long long)atomicAdd(&g_chunk, 1u) * CHUNK_F4; // cur (t0)
        s_base[1] = (long long)atomicAdd(&g_chunk, 1u) * CHUNK_F4; // iter 1 (t1)
        s_base[0] = (long long)atomicAdd(&g_chunk, 1u) * CHUNK_F4; // iter 2 (t2)
    }
    __syncthreads();

    float acc = 0.0f;
    long long base = s_base[2];

    // Prologue: load current chunk into registers
    float4 a0, a1, a2, a3, b0, b1, b2, b3;
    if (base + CHUNK_F4 <= n4) {
        long long i0 = base + threadIdx.x;
        a0 = o4[i0];        b0 = x4[i0];
        a1 = o4[i0 + 256];  b1 = x4[i0 + 256];
        a2 = o4[i0 + 512];  b2 = x4[i0 + 512];
        a3 = o4[i0 + 768];  b3 = x4[i0 + 768];
    } else if (base < n4) {
        for (long long i = base + threadIdx.x; i < n4; i += NUM_THREADS) {
            float4 a = o4[i], b = x4[i];
            float d;
            d = a.x - b.x; acc = fmaf(d, d, acc);
            d = a.y - b.y; acc = fmaf(d, d, acc);
            d = a.z - b.z; acc = fmaf(d, d, acc);
            d = a.w - b.w; acc = fmaf(d, d, acc);
        }
        base = n4;
    }

    // Pipelined steal loop: FMA chunk k while loading chunk k+1.
    // Iteration k reads slot (k&1) and refills that same slot (read again at
    // k+2; the intervening iteration's barrier orders write-before-read).
    int k = 1;
    while (base < n4) {
        long long next = s_base[k & 1];
        __syncthreads();                    // everyone has read slot (k&1)
        if (threadIdx.x == 0)               // refill for iteration k+2
            s_base[k & 1] = (long long)atomicAdd(&g_chunk, 1u) * CHUNK_F4;

        bool full = (next + CHUNK_F4 <= n4);
        float4 na0, na1, na2, na3, nb0, nb1, nb2, nb3;
        if (full) {
            long long i0 = next + threadIdx.x;
            na0 = o4[i0];        nb0 = x4[i0];
            na1 = o4[i0 + 256];  nb1 = x4[i0 + 256];
            na2 = o4[i0 + 512];  nb2 = x4[i0 + 512];
            na3 = o4[i0 + 768];  nb3 = x4[i0 + 768];
        } else if (next < n4) {
            // ragged last chunk: process immediately (scalar)
            for (long long i = next + threadIdx.x; i < n4; i += NUM_THREADS) {
                float4 a = o4[i], b = x4[i];
                float d;
                d = a.x - b.x; acc = fmaf(d, d, acc);
                d = a.y - b.y; acc = fmaf(d, d, acc);
                d = a.z - b.z; acc = fmaf(d, d, acc);
                d = a.w - b.w; acc = fmaf(d, d, acc);
            }
        }
        if (!full) next = n4;               // exit after consuming current

        // Consume current chunk (loaded one iteration ago — latency hidden)
        float d;
        d = a0.x - b0.x; acc = fmaf(d, d, acc);
        d = a0.y - b0.y; acc = fmaf(d, d, acc);
        d = a0.z - b0.z; acc = fmaf(d, d, acc);
        d = a0.w - b0.w; acc = fmaf(d, d, acc);
        d = a1.x - b1.x; acc = fmaf(d, d, acc);
        d = a1.y - b1.y; acc = fmaf(d, d, acc);
        d = a1.z - b1.z; acc = fmaf(d, d, acc);
        d = a1.w - b1.w; acc = fmaf(d, d, acc);
        d = a2.x - b2.x; acc = fmaf(d, d, acc);
        d = a2.y - b2.y; acc = fmaf(d, d, acc);
        d = a2.z - b2.z; acc = fmaf(d, d, acc);
        d = a2.w - b2.w; acc = fmaf(d, d, acc);
        d = a3.x - b3.x; acc = fmaf(d, d, acc);
        d = a3.y - b3.y; acc = fmaf(d, d, acc);
        d = a3.z - b3.z; acc = fmaf(d, d, acc);
        d = a3.w - b3.w; acc = fmaf(d, d, acc);

        a0 = na0; a1 = na1; a2 = na2; a3 = na3;
        b0 = nb0; b1 = nb1; b2 = nb2; b3 = nb3;
        base = next; k++;
    }

    // intra-block reduce
    #pragma unroll
    for (int off = 16; off > 0; off >>= 1)
        acc += __shfl_xor_sync(0xFFFFFFFFu, acc, off);

    __shared__ float warp_sums[NUM_THREADS / 32];
    if (lane == 0) warp_sums[wid] = acc;
    __syncthreads();

    __shared__ bool s_is_last;
    if (threadIdx.x == 0) {
        float v = 0.0f;
        #pragma unroll
        for (int w = 0; w < NUM_THREADS / 32; w++) v += warp_sums[w];
        g_partials[blockIdx.x] = v;
        __threadfence();
        unsigned int t = atomicAdd(&g_ticket, 1u);
        s_is_last = (t == (unsigned int)(gridDim.x - 1));
    }
    __syncthreads();

    if (!s_is_last) return;

    // Last block: sum partials (hot in L2), finalize in double, reset counters.
    __shared__ double s_sums[NUM_THREADS / 32];
    double s = 0.0;
    for (int q = threadIdx.x; q < NUM_BLOCKS; q += NUM_THREADS)
        s += (double)g_partials[q];

    #pragma unroll
    for (int off = 16; off > 0; off >>= 1)
        s += __shfl_xor_sync(0xFFFFFFFFu, s, off);
    if (lane == 0) s_sums[wid] = s;
    __syncthreads();

    if (wid == 0) {
        double v = (lane < NUM_THREADS / 32) ? s_sums[lane] : 0.0;
        #pragma unroll
        for (int off = 4; off > 0; off >>= 1)
            v += __shfl_xor_sync(0xFFFFFFFFu, v, off);
        if (lane == 0) {
            const double LOG_2PI = 1.8378770664093453;
            double noise = (double)noise_p[0];
            double result = -0.5 * nd * LOG_2PI
                          - 0.5 * nd * noise
                          - 0.5 * exp(-2.0 * noise) * v;
            out[0] = (float)result;
            g_ticket = 0u;   // reset for next graph replay
            g_chunk  = 0u;
        }
    }
}

extern "C" void kernel_launch(void* const* d_in, const int* in_sizes, int n_in,
                              void* d_out, int out_size)
{
    const float* o     = (const float*)d_in[0];
    const float* x     = (const float*)d_in[1];
    const float* noise = (const float*)d_in[2];
    float* out = (float*)d_out;

    long long n  = (long long)in_sizes[0];
    long long n4 = n >> 2;

    lik_pipe_kernel<<<NUM_BLOCKS, NUM_THREADS>>>(o, x, noise, out, n4, (double)n);
}

// round 7
// speedup vs baseline: 1.0206x; 1.0206x over previous
#include <cuda_runtime.h>
#include <math.h>

#define NUM_BLOCKS 1184
#define NUM_THREADS 256
#define CHUNK_F4 1024LL   // float4 per dynamic chunk per input (16 KB per input)

__device__ float g_partials[NUM_BLOCKS];
__device__ unsigned int g_ticket;   // zero-init; reset by last block each run
__device__ unsigned int g_chunk;    // zero-init; reset by last block each run

__global__ __launch_bounds__(NUM_THREADS)
void lik_hybrid_kernel(const float* __restrict__ o,
                       const float* __restrict__ x,
                       const float* __restrict__ noise_p,
                       float* __restrict__ out,
                       long long n4, long long n_static, double nd)
{
    const float4* __restrict__ o4 = (const float4*)o;
    const float4* __restrict__ x4 = (const float4*)x;

    __shared__ long long s_base[2];
    int lane = threadIdx.x & 31;
    int wid  = threadIdx.x >> 5;

    // Grab the first dynamic chunk base now — latency hidden under static phase.
    if (threadIdx.x == 0)
        s_base[0] = n_static + (long long)atomicAdd(&g_chunk, 1u) * CHUNK_F4;

    // ---- Static phase: barrier-free grid-stride over the first n_static f4 ----
    float acc = 0.0f;
    long long stride = (long long)gridDim.x * blockDim.x;
    long long i = (long long)blockIdx.x * blockDim.x + threadIdx.x;

    for (; i + stride < n_static; i += 2 * stride) {
        float4 a0 = o4[i];
        float4 b0 = x4[i];
        float4 a1 = o4[i + stride];
        float4 b1 = x4[i + stride];
        float d;
        d = a0.x - b0.x; acc = fmaf(d, d, acc);
        d = a0.y - b0.y; acc = fmaf(d, d, acc);
        d = a0.z - b0.z; acc = fmaf(d, d, acc);
        d = a0.w - b0.w; acc = fmaf(d, d, acc);
        d = a1.x - b1.x; acc = fmaf(d, d, acc);
        d = a1.y - b1.y; acc = fmaf(d, d, acc);
        d = a1.z - b1.z; acc = fmaf(d, d, acc);
        d = a1.w - b1.w; acc = fmaf(d, d, acc);
    }
    for (; i < n_static; i += stride) {
        float4 a = o4[i];
        float4 b = x4[i];
        float d;
        d = a.x - b.x; acc = fmaf(d, d, acc);
        d = a.y - b.y; acc = fmaf(d, d, acc);
        d = a.z - b.z; acc = fmaf(d, d, acc);
        d = a.w - b.w; acc = fmaf(d, d, acc);
    }

    // ---- Dynamic phase: work-stealing over the tail (absorbs CTA spread) ----
    __syncthreads();   // s_base[0] visible
    int parity = 0;

    while (true) {
        long long base = s_base[parity];
        if (threadIdx.x == 0)  // prefetch next base; hidden under this chunk's loads
            s_base[parity ^ 1] = n_static + (long long)atomicAdd(&g_chunk, 1u) * CHUNK_F4;
        if (base >= n4) break;

        long long i0 = base + threadIdx.x;
        if (base + CHUNK_F4 <= n4) {
            float4 a0 = o4[i0];
            float4 b0 = x4[i0];
            float4 a1 = o4[i0 + 256];
            float4 b1 = x4[i0 + 256];
            float4 a2 = o4[i0 + 512];
            float4 b2 = x4[i0 + 512];
            float4 a3 = o4[i0 + 768];
            float4 b3 = x4[i0 + 768];
            float d;
            d = a0.x - b0.x; acc = fmaf(d, d, acc);
            d = a0.y - b0.y; acc = fmaf(d, d, acc);
            d = a0.z - b0.z; acc = fmaf(d, d, acc);
            d = a0.w - b0.w; acc = fmaf(d, d, acc);
            d = a1.x - b1.x; acc = fmaf(d, d, acc);
            d = a1.y - b1.y; acc = fmaf(d, d, acc);
            d = a1.z - b1.z; acc = fmaf(d, d, acc);
            d = a1.w - b1.w; acc = fmaf(d, d, acc);
            d = a2.x - b2.x; acc = fmaf(d, d, acc);
            d = a2.y - b2.y; acc = fmaf(d, d, acc);
            d = a2.z - b2.z; acc = fmaf(d, d, acc);
            d = a2.w - b2.w; acc = fmaf(d, d, acc);
            d = a3.x - b3.x; acc = fmaf(d, d, acc);
            d = a3.y - b3.y; acc = fmaf(d, d, acc);
            d = a3.z - b3.z; acc = fmaf(d, d, acc);
            d = a3.w - b3.w; acc = fmaf(d, d, acc);
        } else {
            for (long long j = i0; j < n4; j += NUM_THREADS) {
                float4 a = o4[j];
                float4 b = x4[j];
                float d;
                d = a.x - b.x; acc = fmaf(d, d, acc);
                d = a.y - b.y; acc = fmaf(d, d, acc);
                d = a.z - b.z; acc = fmaf(d, d, acc);
                d = a.w - b.w; acc = fmaf(d, d, acc);
            }
        }
        __syncthreads();   // next-base write visible; safe to flip
        parity ^= 1;
    }

    // ---- intra-block reduce ----
    #pragma unroll
    for (int off = 16; off > 0; off >>= 1)
        acc += __shfl_xor_sync(0xFFFFFFFFu, acc, off);

    __shared__ float warp_sums[NUM_THREADS / 32];
    if (lane == 0) warp_sums[wid] = acc;
    __syncthreads();

    __shared__ bool s_is_last;
    if (threadIdx.x == 0) {
        float v = 0.0f;
        #pragma unroll
        for (int w = 0; w < NUM_THREADS / 32; w++) v += warp_sums[w];
        g_partials[blockIdx.x] = v;
        __threadfence();
        unsigned int t = atomicAdd(&g_ticket, 1u);
        s_is_last = (t == (unsigned int)(gridDim.x - 1));
    }
    __syncthreads();

    if (!s_is_last) return;

    // ---- Last block: finalize in double, reset counters ----
    __shared__ double s_sums[NUM_THREADS / 32];
    double s = 0.0;
    for (int q = threadIdx.x; q < NUM_BLOCKS; q += NUM_THREADS)
        s += (double)g_partials[q];

    #pragma unroll
    for (int off = 16; off > 0; off >>= 1)
        s += __shfl_xor_sync(0xFFFFFFFFu, s, off);
    if (lane == 0) s_sums[wid] = s;
    __syncthreads();

    if (wid == 0) {
        double v = (lane < NUM_THREADS / 32) ? s_sums[lane] : 0.0;
        #pragma unroll
        for (int off = 4; off > 0; off >>= 1)
            v += __shfl_xor_sync(0xFFFFFFFFu, v, off);
        if (lane == 0) {
            const double LOG_2PI = 1.8378770664093453;
            double noise = (double)noise_p[0];
            double result = -0.5 * nd * LOG_2PI
                          - 0.5 * nd * noise
                          - 0.5 * exp(-2.0 * noise) * v;
            out[0] = (float)result;
            g_ticket = 0u;   // reset for next graph replay
            g_chunk  = 0u;
        }
    }
}

extern "C" void kernel_launch(void* const* d_in, const int* in_sizes, int n_in,
                              void* d_out, int out_size)
{
    const float* o     = (const float*)d_in[0];
    const float* x     = (const float*)d_in[1];
    const float* noise = (const float*)d_in[2];
    float* out = (float*)d_out;

    long long n  = (long long)in_sizes[0];
    long long n4 = n >> 2;

    // Static portion: ~74% of the data, rounded to a multiple of 2*grid stride
    // so the static loop runs its unrolled body uniformly.
    long long T = (long long)NUM_BLOCKS * NUM_THREADS;
    long long n_static = ((n4 * 3) / 4) / (2 * T) * (2 * T);

    lik_hybrid_kernel<<<NUM_BLOCKS, NUM_THREADS>>>(o, x, noise, out,
                                                   n4, n_static, (double)n);
}

// round 8
// speedup vs baseline: 1.0477x; 1.0265x over previous
#include <cuda_runtime.h>
#include <math.h>

#define NUM_BLOCKS 1184
#define NUM_THREADS 256
#define NUM_SLICES 16
#define WCHUNK 128LL          // float4 per warp-chunk per input (2 KB per input)

__device__ float g_partials[NUM_BLOCKS];
__device__ unsigned int g_ticket;                    // zero-init; reset each run
__device__ unsigned int g_counters[NUM_SLICES * 32]; // 128B-strided counters

__global__ __launch_bounds__(NUM_THREADS)
void lik_warpsteal_kernel(const float* __restrict__ o,
                          const float* __restrict__ x,
                          const float* __restrict__ noise_p,
                          float* __restrict__ out,
                          long long n4, double nd)
{
    const float4* __restrict__ o4 = (const float4*)o;
    const float4* __restrict__ x4 = (const float4*)x;

    int lane = threadIdx.x & 31;
    int wid  = threadIdx.x >> 5;

    // Slice assignment: 74 CTAs per slice, 16 sharded counters (128B apart).
    int slice = blockIdx.x & (NUM_SLICES - 1);
    long long slice_len = (n4 + NUM_SLICES - 1) / NUM_SLICES;
    // round slice_len up to chunk multiple so slice starts are chunk-aligned
    slice_len = ((slice_len + WCHUNK - 1) / WCHUNK) * WCHUNK;
    long long s_begin = (long long)slice * slice_len;
    long long s_end   = s_begin + slice_len;
    if (s_end > n4) s_end = n4;
    unsigned int* ctr = &g_counters[slice * 32];

    float acc = 0.0f;

    // First steal
    unsigned int t0 = 0;
    if (lane == 0) t0 = atomicAdd(ctr, 1u);
    t0 = __shfl_sync(0xFFFFFFFFu, t0, 0);
    long long cur = s_begin + (long long)t0 * WCHUNK;

    while (cur < s_end) {
        long long nxt;
        if (cur + WCHUNK <= s_end) {
            // full warp-chunk: 4 float4 per lane per input, 8 LDG.128 in flight
            long long i0 = cur + lane;
            float4 a0 = o4[i0];
            float4 b0 = x4[i0];
            float4 a1 = o4[i0 + 32];
            float4 b1 = x4[i0 + 32];
            float4 a2 = o4[i0 + 64];
            float4 b2 = x4[i0 + 64];
            float4 a3 = o4[i0 + 96];
            float4 b3 = x4[i0 + 96];

            // steal next chunk while loads are in flight
            unsigned int t = 0;
            if (lane == 0) t = atomicAdd(ctr, 1u);
            t = __shfl_sync(0xFFFFFFFFu, t, 0);
            nxt = s_begin + (long long)t * WCHUNK;

            float d;
            d = a0.x - b0.x; acc = fmaf(d, d, acc);
            d = a0.y - b0.y; acc = fmaf(d, d, acc);
            d = a0.z - b0.z; acc = fmaf(d, d, acc);
            d = a0.w - b0.w; acc = fmaf(d, d, acc);
            d = a1.x - b1.x; acc = fmaf(d, d, acc);
            d = a1.y - b1.y; acc = fmaf(d, d, acc);
            d = a1.z - b1.z; acc = fmaf(d, d, acc);
            d = a1.w - b1.w; acc = fmaf(d, d, acc);
            d = a2.x - b2.x; acc = fmaf(d, d, acc);
            d = a2.y - b2.y; acc = fmaf(d, d, acc);
            d = a2.z - b2.z; acc = fmaf(d, d, acc);
            d = a2.w - b2.w; acc = fmaf(d, d, acc);
            d = a3.x - b3.x; acc = fmaf(d, d, acc);
            d = a3.y - b3.y; acc = fmaf(d, d, acc);
            d = a3.z - b3.z; acc = fmaf(d, d, acc);
            d = a3.w - b3.w; acc = fmaf(d, d, acc);
        } else {
            // ragged tail of the slice (at most once per warp)
            for (long long j = cur + lane; j < s_end; j += 32) {
                float4 a = o4[j];
                float4 b = x4[j];
                float d;
                d = a.x - b.x; acc = fmaf(d, d, acc);
                d = a.y - b.y; acc = fmaf(d, d, acc);
                d = a.z - b.z; acc = fmaf(d, d, acc);
                d = a.w - b.w; acc = fmaf(d, d, acc);
            }
            unsigned int t = 0;
            if (lane == 0) t = atomicAdd(ctr, 1u);
            t = __shfl_sync(0xFFFFFFFFu, t, 0);
            nxt = s_begin + (long long)t * WCHUNK;
        }
        cur = nxt;
    }

    // ---- intra-block reduce ----
    #pragma unroll
    for (int off = 16; off > 0; off >>= 1)
        acc += __shfl_xor_sync(0xFFFFFFFFu, acc, off);

    __shared__ float warp_sums[NUM_THREADS / 32];
    if (lane == 0) warp_sums[wid] = acc;
    __syncthreads();

    __shared__ bool s_is_last;
    if (threadIdx.x == 0) {
        float v = 0.0f;
        #pragma unroll
        for (int w = 0; w < NUM_THREADS / 32; w++) v += warp_sums[w];
        g_partials[blockIdx.x] = v;
        __threadfence();
        unsigned int t = atomicAdd(&g_ticket, 1u);
        s_is_last = (t == (unsigned int)(gridDim.x - 1));
    }
    __syncthreads();

    if (!s_is_last) return;

    // ---- Last block: finalize in double, reset counters ----
    __shared__ double s_sums[NUM_THREADS / 32];
    double s = 0.0;
    for (int q = threadIdx.x; q < NUM_BLOCKS; q += NUM_THREADS)
        s += (double)g_partials[q];

    #pragma unroll
    for (int off = 16; off > 0; off >>= 1)
        s += __shfl_xor_sync(0xFFFFFFFFu, s, off);
    if (lane == 0) s_sums[wid] = s;
    __syncthreads();

    if (wid == 0) {
        double v = (lane < NUM_THREADS / 32) ? s_sums[lane] : 0.0;
        #pragma unroll
        for (int off = 4; off > 0; off >>= 1)
            v += __shfl_xor_sync(0xFFFFFFFFu, v, off);
        if (lane == 0) {
            const double LOG_2PI = 1.8378770664093453;
            double noise = (double)noise_p[0];
            double result = -0.5 * nd * LOG_2PI
                          - 0.5 * nd * noise
                          - 0.5 * exp(-2.0 * noise) * v;
            out[0] = (float)result;
            g_ticket = 0u;
            #pragma unroll
            for (int c = 0; c < NUM_SLICES; c++)
                g_counters[c * 32] = 0u;     // reset for next graph replay
        }
    }
}

extern "C" void kernel_launch(void* const* d_in, const int* in_sizes, int n_in,
                              void* d_out, int out_size)
{
    const float* o     = (const float*)d_in[0];
    const float* x     = (const float*)d_in[1];
    const float* noise = (const float*)d_in[2];
    float* out = (float*)d_out;

    long long n  = (long long)in_sizes[0];
    long long n4 = n >> 2;

    lik_warpsteal_kernel<<<NUM_BLOCKS, NUM_THREADS>>>(o, x, noise, out,
                                                      n4, (double)n);
}

// round 11
// speedup vs baseline: 1.0636x; 1.0152x over previous
#include <cuda_runtime.h>
#include <math.h>

#define NUM_BLOCKS 1184
#define NUM_THREADS 256
#define CHUNK_F4 1024LL   // float4 per chunk per input (16 KB per input)

__device__ float g_partials[NUM_BLOCKS];
__device__ unsigned int g_ticket;   // zero-init; reset by last block each run
__device__ unsigned int g_chunk;    // zero-init; reset by last block each run

__global__ __launch_bounds__(NUM_THREADS)
void lik_steal_cs_kernel(const float* __restrict__ o,
                         const float* __restrict__ x,
                         const float* __restrict__ noise_p,
                         float* __restrict__ out,
                         long long n4, double nd)
{
    const float4* __restrict__ o4 = (const float4*)o;
    const float4* __restrict__ x4 = (const float4*)x;

    __shared__ long long s_base[2];
    int lane = threadIdx.x & 31;
    int wid  = threadIdx.x >> 5;

    if (threadIdx.x == 0)
        s_base[0] = (long long)atomicAdd(&g_chunk, 1u) * CHUNK_F4;
    __syncthreads();

    float acc = 0.0f;
    int parity = 0;

    while (true) {
        long long base = s_base[parity];
        // Prefetch next chunk base — atomic latency hidden under this chunk's loads
        if (threadIdx.x == 0)
            s_base[parity ^ 1] = (long long)atomicAdd(&g_chunk, 1u) * CHUNK_F4;
        if (base >= n4) break;

        long long i0 = base + threadIdx.x;
        if (base + CHUNK_F4 <= n4) {
            // full chunk: 4 float4 per thread per input, streaming (evict-first) loads
            float4 a0 = __ldcs(&o4[i0]);
            float4 b0 = __ldcs(&x4[i0]);
            float4 a1 = __ldcs(&o4[i0 + 256]);
            float4 b1 = __ldcs(&x4[i0 + 256]);
            float4 a2 = __ldcs(&o4[i0 + 512]);
            float4 b2 = __ldcs(&x4[i0 + 512]);
            float4 a3 = __ldcs(&o4[i0 + 768]);
            float4 b3 = __ldcs(&x4[i0 + 768]);
            float d;
            d = a0.x - b0.x; acc = fmaf(d, d, acc);
            d = a0.y - b0.y; acc = fmaf(d, d, acc);
            d = a0.z - b0.z; acc = fmaf(d, d, acc);
            d = a0.w - b0.w; acc = fmaf(d, d, acc);
            d = a1.x - b1.x; acc = fmaf(d, d, acc);
            d = a1.y - b1.y; acc = fmaf(d, d, acc);
            d = a1.z - b1.z; acc = fmaf(d, d, acc);
            d = a1.w - b1.w; acc = fmaf(d, d, acc);
            d = a2.x - b2.x; acc = fmaf(d, d, acc);
            d = a2.y - b2.y; acc = fmaf(d, d, acc);
            d = a2.z - b2.z; acc = fmaf(d, d, acc);
            d = a2.w - b2.w; acc = fmaf(d, d, acc);
            d = a3.x - b3.x; acc = fmaf(d, d, acc);
            d = a3.y - b3.y; acc = fmaf(d, d, acc);
            d = a3.z - b3.z; acc = fmaf(d, d, acc);
            d = a3.w - b3.w; acc = fmaf(d, d, acc);
        } else {
            // ragged tail chunk
            for (long long i = i0; i < n4; i += NUM_THREADS) {
                float4 a = __ldcs(&o4[i]);
                float4 b = __ldcs(&x4[i]);
                float d;
                d = a.x - b.x; acc = fmaf(d, d, acc);
                d = a.y - b.y; acc = fmaf(d, d, acc);
                d = a.z - b.z; acc = fmaf(d, d, acc);
                d = a.w - b.w; acc = fmaf(d, d, acc);
            }
        }
        __syncthreads();   // next-base write visible; safe to flip
        parity ^= 1;
    }

    // intra-block reduce
    #pragma unroll
    for (int off = 16; off > 0; off >>= 1)
        acc += __shfl_xor_sync(0xFFFFFFFFu, acc, off);

    __shared__ float warp_sums[NUM_THREADS / 32];
    if (lane == 0) warp_sums[wid] = acc;
    __syncthreads();

    __shared__ bool s_is_last;
    if (threadIdx.x == 0) {
        float v = 0.0f;
        #pragma unroll
        for (int w = 0; w < NUM_THREADS / 32; w++) v += warp_sums[w];
        g_partials[blockIdx.x] = v;
        __threadfence();
        unsigned int t = atomicAdd(&g_ticket, 1u);
        s_is_last = (t == (unsigned int)(gridDim.x - 1));
    }
    __syncthreads();

    if (!s_is_last) return;

    // Last block: sum partials (hot in L2), finalize in double, reset counters.
    __shared__ double s_sums[NUM_THREADS / 32];
    double s = 0.0;
    for (int k = threadIdx.x; k < NUM_BLOCKS; k += NUM_THREADS)
        s += (double)g_partials[k];

    #pragma unroll
    for (int off = 16; off > 0; off >>= 1)
        s += __shfl_xor_sync(0xFFFFFFFFu, s, off);
    if (lane == 0) s_sums[wid] = s;
    __syncthreads();

    if (wid == 0) {
        double v = (lane < NUM_THREADS / 32) ? s_sums[lane] : 0.0;
        #pragma unroll
        for (int off = 4; off > 0; off >>= 1)
            v += __shfl_xor_sync(0xFFFFFFFFu, v, off);
        if (lane == 0) {
            const double LOG_2PI = 1.8378770664093453;
            double noise = (double)noise_p[0];
            double result = -0.5 * nd * LOG_2PI
                          - 0.5 * nd * noise
                          - 0.5 * exp(-2.0 * noise) * v;
            out[0] = (float)result;
            g_ticket = 0u;   // reset for next graph replay
            g_chunk  = 0u;
        }
    }
}

extern "C" void kernel_launch(void* const* d_in, const int* in_sizes, int n_in,
                              void* d_out, int out_size)
{
    const float* o     = (const float*)d_in[0];
    const float* x     = (const float*)d_in[1];
    const float* noise = (const float*)d_in[2];
    float* out = (float*)d_out;

    long long n  = (long long)in_sizes[0];
    long long n4 = n >> 2;

    lik_steal_cs_kernel<<<NUM_BLOCKS, NUM_THREADS>>>(o, x, noise, out, n4, (double)n);
}

// round 12
// speedup vs baseline: 1.0665x; 1.0027x over previous
#include <cuda_runtime.h>
#include <math.h>

#define NUM_BLOCKS 1184
#define NUM_THREADS 256
#define CHUNK_F4 2048LL   // float4 per chunk per input (32 KB per input)

__device__ float g_partials[NUM_BLOCKS];
__device__ unsigned int g_ticket;   // zero-init; reset by last block each run
__device__ unsigned int g_chunk;    // zero-init; reset by last block each run

__global__ __launch_bounds__(NUM_THREADS)
void lik_steal_cs2_kernel(const float* __restrict__ o,
                          const float* __restrict__ x,
                          const float* __restrict__ noise_p,
                          float* __restrict__ out,
                          long long n4, double nd)
{
    const float4* __restrict__ o4 = (const float4*)o;
    const float4* __restrict__ x4 = (const float4*)x;

    __shared__ long long s_base[2];
    int lane = threadIdx.x & 31;
    int wid  = threadIdx.x >> 5;

    if (threadIdx.x == 0)
        s_base[0] = (long long)atomicAdd(&g_chunk, 1u) * CHUNK_F4;
    __syncthreads();

    float acc = 0.0f;
    int parity = 0;

    while (true) {
        long long base = s_base[parity];
        // Prefetch next chunk base — atomic latency hidden under this chunk's loads
        if (threadIdx.x == 0)
            s_base[parity ^ 1] = (long long)atomicAdd(&g_chunk, 1u) * CHUNK_F4;
        if (base >= n4) break;

        if (base + CHUNK_F4 <= n4) {
            // full 32KB-per-input chunk: two passes of 4 float4 per thread per input
            #pragma unroll
            for (int half = 0; half < 2; half++) {
                long long i0 = base + half * 1024 + threadIdx.x;
                float4 a0 = __ldcs(&o4[i0]);
                float4 b0 = __ldcs(&x4[i0]);
                float4 a1 = __ldcs(&o4[i0 + 256]);
                float4 b1 = __ldcs(&x4[i0 + 256]);
                float4 a2 = __ldcs(&o4[i0 + 512]);
                float4 b2 = __ldcs(&x4[i0 + 512]);
                float4 a3 = __ldcs(&o4[i0 + 768]);
                float4 b3 = __ldcs(&x4[i0 + 768]);
                float d;
                d = a0.x - b0.x; acc = fmaf(d, d, acc);
                d = a0.y - b0.y; acc = fmaf(d, d, acc);
                d = a0.z - b0.z; acc = fmaf(d, d, acc);
                d = a0.w - b0.w; acc = fmaf(d, d, acc);
                d = a1.x - b1.x; acc = fmaf(d, d, acc);
                d = a1.y - b1.y; acc = fmaf(d, d, acc);
                d = a1.z - b1.z; acc = fmaf(d, d, acc);
                d = a1.w - b1.w; acc = fmaf(d, d, acc);
                d = a2.x - b2.x; acc = fmaf(d, d, acc);
                d = a2.y - b2.y; acc = fmaf(d, d, acc);
                d = a2.z - b2.z; acc = fmaf(d, d, acc);
                d = a2.w - b2.w; acc = fmaf(d, d, acc);
                d = a3.x - b3.x; acc = fmaf(d, d, acc);
                d = a3.y - b3.y; acc = fmaf(d, d, acc);
                d = a3.z - b3.z; acc = fmaf(d, d, acc);
                d = a3.w - b3.w; acc = fmaf(d, d, acc);
            }
        } else {
            // ragged tail chunk
            for (long long i = base + threadIdx.x; i < n4; i += NUM_THREADS) {
                float4 a = __ldcs(&o4[i]);
                float4 b = __ldcs(&x4[i]);
                float d;
                d = a.x - b.x; acc = fmaf(d, d, acc);
                d = a.y - b.y; acc = fmaf(d, d, acc);
                d = a.z - b.z; acc = fmaf(d, d, acc);
                d = a.w - b.w; acc = fmaf(d, d, acc);
            }
        }
        __syncthreads();   // next-base write visible; safe to flip
        parity ^= 1;
    }

    // intra-block reduce
    #pragma unroll
    for (int off = 16; off > 0; off >>= 1)
        acc += __shfl_xor_sync(0xFFFFFFFFu, acc, off);

    __shared__ float warp_sums[NUM_THREADS / 32];
    if (lane == 0) warp_sums[wid] = acc;
    __syncthreads();

    __shared__ bool s_is_last;
    if (threadIdx.x == 0) {
        float v = 0.0f;
        #pragma unroll
        for (int w = 0; w < NUM_THREADS / 32; w++) v += warp_sums[w];
        g_partials[blockIdx.x] = v;
        __threadfence();
        unsigned int t = atomicAdd(&g_ticket, 1u);
        s_is_last = (t == (unsigned int)(gridDim.x - 1));
    }
    __syncthreads();

    if (!s_is_last) return;

    // Last block: sum partials (hot in L2), finalize in double, reset counters.
    __shared__ double s_sums[NUM_THREADS / 32];
    double s = 0.0;
    for (int k = threadIdx.x; k < NUM_BLOCKS; k += NUM_THREADS)
        s += (double)g_partials[k];

    #pragma unroll
    for (int off = 16; off > 0; off >>= 1)
        s += __shfl_xor_sync(0xFFFFFFFFu, s, off);
    if (lane == 0) s_sums[wid] = s;
    __syncthreads();

    if (wid == 0) {
        double v = (lane < NUM_THREADS / 32) ? s_sums[lane] : 0.0;
        #pragma unroll
        for (int off = 4; off > 0; off >>= 1)
            v += __shfl_xor_sync(0xFFFFFFFFu, v, off);
        if (lane == 0) {
            const double LOG_2PI = 1.8378770664093453;
            double noise = (double)noise_p[0];
            double result = -0.5 * nd * LOG_2PI
                          - 0.5 * nd * noise
                          - 0.5 * exp(-2.0 * noise) * v;
            out[0] = (float)result;
            g_ticket = 0u;   // reset for next graph replay
            g_chunk  = 0u;
        }
    }
}

extern "C" void kernel_launch(void* const* d_in, const int* in_sizes, int n_in,
                              void* d_out, int out_size)
{
    const float* o     = (const float*)d_in[0];
    const float* x     = (const float*)d_in[1];
    const float* noise = (const float*)d_in[2];
    float* out = (float*)d_out;

    long long n  = (long long)in_sizes[0];
    long long n4 = n >> 2;

    lik_steal_cs2_kernel<<<NUM_BLOCKS, NUM_THREADS>>>(o, x, noise, out, n4, (double)n);
}